// round 1
// baseline (speedup 1.0000x reference)
#include <cuda_runtime.h>
#include <cuda_bf16.h>

// Problem constants (fixed shapes from setup_inputs)
#define BATCH 4
#define CIN   64
#define HNUM  96
#define WNUM  96
#define G     8
#define OG    8
#define IG    8
#define KW    7
#define PAD   3

// Tiling: block = 256 threads = 8 rows x 32 cols of output pixels.
// Warp covers a full 32-wide row -> conflict-free SMEM reads.
#define TH 8
#define TW 32
#define HH (TH + KW - 1)   // 14
#define HW (TW + KW - 1)   // 38
#define HSTR 40            // padded row stride (floats)

#define PLANE (HNUM * WNUM) // 9216

__global__ __launch_bounds__(256)
void attn_fused_kernel(const float* __restrict__ x,
                       const float* __restrict__ wq,
                       const float* __restrict__ wk,
                       const float* __restrict__ wv,
                       const float* __restrict__ h_emb,
                       const float* __restrict__ w_emb,
                       float* __restrict__ out)
{
    __shared__ float ks_s[OG][HH][HSTR];   // 8*14*40*4 = 17.9 KB
    __shared__ float vs_s[OG][HH][HSTR];   // 17.9 KB
    __shared__ float wq_s[OG * IG];
    __shared__ float wk_s[OG * IG];
    __shared__ float wv_s[OG * IG];
    __shared__ float he_s[(OG / 2) * KW];  // 28
    __shared__ float we_s[(OG / 2) * KW];  // 28

    const int tid = threadIdx.x;
    const int bz  = blockIdx.z;          // b*G + g
    const int b   = bz >> 3;
    const int g   = bz & 7;
    const int h0  = blockIdx.y * TH;
    const int w0  = blockIdx.x * TW;

    // --- load per-group weights + embeddings into SMEM ---
    if (tid < 64) {
        wq_s[tid] = wq[g * 64 + tid];
        wk_s[tid] = wk[g * 64 + tid];
        wv_s[tid] = wv[g * 64 + tid];
    } else if (tid >= 64 && tid < 92) {
        he_s[tid - 64] = h_emb[g * 28 + (tid - 64)];
    } else if (tid >= 96 && tid < 124) {
        we_s[tid - 96] = w_emb[g * 28 + (tid - 96)];
    }
    __syncthreads();

    const float* xg = x + (size_t)(b * CIN + g * IG) * PLANE;

    // --- phase 1: compute k,v conv over haloed tile into SMEM ---
    for (int p = tid; p < HH * HW; p += 256) {
        const int yy = p / HW;
        const int xx = p - yy * HW;
        const int gy = h0 + yy - PAD;
        const int gx = w0 + xx - PAD;
        const bool inb = ((unsigned)gy < HNUM) & ((unsigned)gx < WNUM);
        const float* xb = xg + gy * WNUM + gx;
        float xi[IG];
        #pragma unroll
        for (int i = 0; i < IG; i++)
            xi[i] = inb ? __ldg(xb + i * PLANE) : 0.0f;
        #pragma unroll
        for (int c = 0; c < OG; c++) {
            float kc = 0.0f, vc = 0.0f;
            #pragma unroll
            for (int i = 0; i < IG; i++) {
                kc = fmaf(wk_s[c * IG + i], xi[i], kc);
                vc = fmaf(wv_s[c * IG + i], xi[i], vc);
            }
            ks_s[c][yy][xx] = kc;
            vs_s[c][yy][xx] = vc;
        }
    }
    __syncthreads();

    // --- phase 2: attention for one pixel per thread, 8 channels ---
    const int x_ = tid & 31;
    const int y_ = tid >> 5;
    const int gh = h0 + y_;
    const int gw = w0 + x_;

    float xi[IG];
    {
        const float* xb = xg + gh * WNUM + gw;
        #pragma unroll
        for (int i = 0; i < IG; i++) xi[i] = __ldg(xb + i * PLANE);
    }

    float* op = out + ((size_t)(b * CIN + g * OG) * HNUM + gh) * WNUM + gw;

    const float LOG2E = 1.4426950408889634f;

    // channels 0..3: emb varies along patch ROW (di)
    #pragma unroll 1
    for (int c = 0; c < OG / 2; c++) {
        float qs = 0.0f;
        #pragma unroll
        for (int i = 0; i < IG; i++) qs = fmaf(wq_s[c * IG + i], xi[i], qs);
        qs *= LOG2E;
        float qe[KW];
        #pragma unroll
        for (int t = 0; t < KW; t++) qe[t] = qs * he_s[c * KW + t];

        float ssum = 0.0f, acc = 0.0f;
        #pragma unroll
        for (int di = 0; di < KW; di++) {
            #pragma unroll
            for (int dj = 0; dj < KW; dj++) {
                float kv = ks_s[c][y_ + di][x_ + dj];
                float vv = vs_s[c][y_ + di][x_ + dj];
                float l  = fmaf(qs, kv, qe[di]);
                float e;
                asm("ex2.approx.f32 %0, %1;" : "=f"(e) : "f"(l));
                ssum += e;
                acc = fmaf(e, vv, acc);
            }
        }
        op[(size_t)c * PLANE] = __fdividef(acc, ssum);
    }

    // channels 4..7: emb varies along patch COL (dj)
    #pragma unroll 1
    for (int c = OG / 2; c < OG; c++) {
        float qs = 0.0f;
        #pragma unroll
        for (int i = 0; i < IG; i++) qs = fmaf(wq_s[c * IG + i], xi[i], qs);
        qs *= LOG2E;
        float qe[KW];
        #pragma unroll
        for (int t = 0; t < KW; t++) qe[t] = qs * we_s[(c - OG / 2) * KW + t];

        float ssum = 0.0f, acc = 0.0f;
        #pragma unroll
        for (int di = 0; di < KW; di++) {
            #pragma unroll
            for (int dj = 0; dj < KW; dj++) {
                float kv = ks_s[c][y_ + di][x_ + dj];
                float vv = vs_s[c][y_ + di][x_ + dj];
                float l  = fmaf(qs, kv, qe[dj]);
                float e;
                asm("ex2.approx.f32 %0, %1;" : "=f"(e) : "f"(l));
                ssum += e;
                acc = fmaf(e, vv, acc);
            }
        }
        op[(size_t)c * PLANE] = __fdividef(acc, ssum);
    }
}

extern "C" void kernel_launch(void* const* d_in, const int* in_sizes, int n_in,
                              void* d_out, int out_size)
{
    const float* x     = (const float*)d_in[0];
    const float* wq    = (const float*)d_in[1];
    const float* wk    = (const float*)d_in[2];
    const float* wv    = (const float*)d_in[3];
    const float* h_emb = (const float*)d_in[4];
    const float* w_emb = (const float*)d_in[5];
    float* out = (float*)d_out;

    dim3 grid(WNUM / TW, HNUM / TH, BATCH * G);  // (3, 12, 32)
    dim3 block(256);
    attn_fused_kernel<<<grid, block>>>(x, wq, wk, wv, h_emb, w_emb, out);
}

// round 2
// speedup vs baseline: 1.1153x; 1.1153x over previous
#include <cuda_runtime.h>
#include <cuda_bf16.h>

// Problem constants (fixed shapes from setup_inputs)
#define BATCH 4
#define CIN   64
#define HNUM  96
#define WNUM  96
#define G     8
#define OG    8
#define IG    8
#define KW    7
#define PAD   3

#define PLANE (HNUM * WNUM) // 9216

// Tiling: block = 192 threads = 12 rows x 16 thread-cols, 2 px per thread in w.
#define TH 12
#define TW 32
#define TC 16               // thread columns (each owns 2 pixels)
#define NTHREADS 192
#define HH (TH + KW - 1)    // 18
#define HWD (TW + KW - 1)   // 38
#define KVSTR 80            // floats per row: 38 px * 2 (k,v interleaved) = 76, pad to 80

__global__ __launch_bounds__(NTHREADS)
void attn_fused_kernel(const float* __restrict__ x,
                       const float* __restrict__ wq,
                       const float* __restrict__ wk,
                       const float* __restrict__ wv,
                       const float* __restrict__ h_emb,
                       const float* __restrict__ w_emb,
                       float* __restrict__ out)
{
    // k,v interleaved per pixel: [ch][row][2*col + {k,v}]
    __shared__ __align__(16) float kv_s[OG][HH][KVSTR];   // 8*18*80*4 = 45 KB
    __shared__ float wq_s[OG * IG];
    __shared__ float wk_s[OG * IG];
    __shared__ float wv_s[OG * IG];
    __shared__ float he_s[(OG / 2) * KW];
    __shared__ float we_s[(OG / 2) * KW];

    const int tid = threadIdx.x;
    const int bz  = blockIdx.z;          // b*G + g
    const int b   = bz >> 3;
    const int g   = bz & 7;
    const int h0  = blockIdx.y * TH;
    const int w0  = blockIdx.x * TW;

    // --- load per-group weights + embeddings into SMEM ---
    if (tid < 64) {
        wq_s[tid] = wq[g * 64 + tid];
        wk_s[tid] = wk[g * 64 + tid];
        wv_s[tid] = wv[g * 64 + tid];
    } else if (tid >= 64 && tid < 92) {
        he_s[tid - 64] = h_emb[g * 28 + (tid - 64)];
    } else if (tid >= 96 && tid < 124) {
        we_s[tid - 96] = w_emb[g * 28 + (tid - 96)];
    }
    __syncthreads();

    const float* xg = x + (size_t)(b * CIN + g * IG) * PLANE;

    // --- phase 1: grouped 1x1 conv k,v over haloed tile -> interleaved SMEM ---
    for (int p = tid; p < HH * HWD; p += NTHREADS) {
        const int yy = p / HWD;
        const int xx = p - yy * HWD;
        const int gy = h0 + yy - PAD;
        const int gx = w0 + xx - PAD;
        const bool inb = ((unsigned)gy < HNUM) & ((unsigned)gx < WNUM);
        const float* xb = xg + gy * WNUM + gx;
        float xi[IG];
        #pragma unroll
        for (int i = 0; i < IG; i++)
            xi[i] = inb ? __ldg(xb + i * PLANE) : 0.0f;
        #pragma unroll
        for (int c = 0; c < OG; c++) {
            float kc = 0.0f, vc = 0.0f;
            #pragma unroll
            for (int i = 0; i < IG; i++) {
                kc = fmaf(wk_s[c * IG + i], xi[i], kc);
                vc = fmaf(wv_s[c * IG + i], xi[i], vc);
            }
            *(float2*)&kv_s[c][yy][2 * xx] = make_float2(kc, vc);
        }
    }
    __syncthreads();

    // --- phase 2: attention; each thread owns 2 adjacent pixels, 8 channels ---
    const int tc = tid & (TC - 1);
    const int y_ = tid >> 4;
    const int x_ = 2 * tc;         // first pixel column within tile
    const int gh = h0 + y_;
    const int gw = w0 + x_;

    float xi0[IG], xi1[IG];
    {
        const float* xb = xg + gh * WNUM + gw;
        #pragma unroll
        for (int i = 0; i < IG; i++) {
            float2 t = __ldg((const float2*)(xb + i * PLANE));
            xi0[i] = t.x; xi1[i] = t.y;
        }
    }

    float* op = out + ((size_t)(b * CIN + g * OG) * HNUM + gh) * WNUM + gw;

    const float LOG2E = 1.4426950408889634f;

    // channels 0..3: emb varies along patch ROW (di)
    #pragma unroll 1
    for (int c = 0; c < OG / 2; c++) {
        float qs0 = 0.0f, qs1 = 0.0f;
        #pragma unroll
        for (int i = 0; i < IG; i++) {
            qs0 = fmaf(wq_s[c * IG + i], xi0[i], qs0);
            qs1 = fmaf(wq_s[c * IG + i], xi1[i], qs1);
        }
        qs0 *= LOG2E; qs1 *= LOG2E;

        float ssum0 = 0.0f, acc0 = 0.0f, ssum1 = 0.0f, acc1 = 0.0f;
        #pragma unroll
        for (int di = 0; di < KW; di++) {
            const float eh = he_s[c * KW + di];
            const float qe0 = qs0 * eh, qe1 = qs1 * eh;
            const float4* rp = (const float4*)&kv_s[c][y_ + di][2 * x_];
            float4 a0 = rp[0], a1 = rp[1], a2 = rp[2], a3 = rp[3];
            float kk[8] = {a0.x, a0.z, a1.x, a1.z, a2.x, a2.z, a3.x, a3.z};
            float vv[8] = {a0.y, a0.w, a1.y, a1.w, a2.y, a2.w, a3.y, a3.w};
            #pragma unroll
            for (int dj = 0; dj < KW; dj++) {
                float e0;
                asm("ex2.approx.f32 %0, %1;" : "=f"(e0) : "f"(fmaf(qs0, kk[dj], qe0)));
                ssum0 += e0; acc0 = fmaf(e0, vv[dj], acc0);
                float e1;
                asm("ex2.approx.f32 %0, %1;" : "=f"(e1) : "f"(fmaf(qs1, kk[dj + 1], qe1)));
                ssum1 += e1; acc1 = fmaf(e1, vv[dj + 1], acc1);
            }
        }
        float2 o = make_float2(__fdividef(acc0, ssum0), __fdividef(acc1, ssum1));
        *(float2*)&op[(size_t)c * PLANE] = o;
    }

    // channels 4..7: emb varies along patch COL (dj)
    #pragma unroll 1
    for (int c = OG / 2; c < OG; c++) {
        float qs0 = 0.0f, qs1 = 0.0f;
        #pragma unroll
        for (int i = 0; i < IG; i++) {
            qs0 = fmaf(wq_s[c * IG + i], xi0[i], qs0);
            qs1 = fmaf(wq_s[c * IG + i], xi1[i], qs1);
        }
        qs0 *= LOG2E; qs1 *= LOG2E;

        float qe0a[KW], qe1a[KW];
        #pragma unroll
        for (int t = 0; t < KW; t++) {
            const float ew = we_s[(c - OG / 2) * KW + t];
            qe0a[t] = qs0 * ew;
            qe1a[t] = qs1 * ew;
        }

        float ssum0 = 0.0f, acc0 = 0.0f, ssum1 = 0.0f, acc1 = 0.0f;
        #pragma unroll
        for (int di = 0; di < KW; di++) {
            const float4* rp = (const float4*)&kv_s[c][y_ + di][2 * x_];
            float4 a0 = rp[0], a1 = rp[1], a2 = rp[2], a3 = rp[3];
            float kk[8] = {a0.x, a0.z, a1.x, a1.z, a2.x, a2.z, a3.x, a3.z};
            float vv[8] = {a0.y, a0.w, a1.y, a1.w, a2.y, a2.w, a3.y, a3.w};
            #pragma unroll
            for (int dj = 0; dj < KW; dj++) {
                float e0;
                asm("ex2.approx.f32 %0, %1;" : "=f"(e0) : "f"(fmaf(qs0, kk[dj], qe0a[dj])));
                ssum0 += e0; acc0 = fmaf(e0, vv[dj], acc0);
                float e1;
                asm("ex2.approx.f32 %0, %1;" : "=f"(e1) : "f"(fmaf(qs1, kk[dj + 1], qe1a[dj])));
                ssum1 += e1; acc1 = fmaf(e1, vv[dj + 1], acc1);
            }
        }
        float2 o = make_float2(__fdividef(acc0, ssum0), __fdividef(acc1, ssum1));
        *(float2*)&op[(size_t)c * PLANE] = o;
    }
}

extern "C" void kernel_launch(void* const* d_in, const int* in_sizes, int n_in,
                              void* d_out, int out_size)
{
    const float* x     = (const float*)d_in[0];
    const float* wq    = (const float*)d_in[1];
    const float* wk    = (const float*)d_in[2];
    const float* wv    = (const float*)d_in[3];
    const float* h_emb = (const float*)d_in[4];
    const float* w_emb = (const float*)d_in[5];
    float* out = (float*)d_out;

    dim3 grid(WNUM / TW, HNUM / TH, BATCH * G);  // (3, 8, 32)
    dim3 block(NTHREADS);
    attn_fused_kernel<<<grid, block>>>(x, wq, wk, wv, h_emb, w_emb, out);
}